// round 10
// baseline (speedup 1.0000x reference)
#include <cuda_runtime.h>
#include <cuda_fp16.h>
#include <cstdint>

// CFConv fused via mma.sync fp16 (m16n8k16, fp32 accum).
// Warp-PAIR tiles: each pair owns 64 edges; each warp computes 64 edges x 32
// dims (its N-half) -> B-fragment smem traffic per edge halves.
// out[dst] += nw[src] * ( ssp(rbf @ W1 + b1) @ W2 + b2 )

static constexpr int TILE    = 256;   // edges per CTA-tile (64 per warp-pair)
static constexpr int THREADS = 256;   // 8 warps = 4 pairs
static constexpr int STRIDE  = 72;    // fp32 row stride

// shared layout (floats)
static constexpr int SBUF_OFF = 0;                    // 256 x 72 fp32
static constexpr int W1F_OFF  = TILE * STRIDE;        // 18432: 512 uint4 fp16 frags
static constexpr int W2F_OFF  = W1F_OFF + 2048;       // 20480
static constexpr int B1_OFF   = W2F_OFF + 2048;       // 22528
static constexpr int B2_OFF   = B1_OFF + 64;          // 22592
static constexpr int SMEM_FLOATS = B2_OFF + 64;       // 22656
static constexpr int SMEM_BYTES  = SMEM_FLOATS * 4;   // 90624

__device__ __forceinline__ uint32_t h2(float lo, float hi) {
    uint32_t d;   // first PTX src -> upper half
    asm("cvt.rn.f16x2.f32 %0, %1, %2;" : "=r"(d) : "f"(hi), "f"(lo));
    return d;
}
__device__ __forceinline__ uint32_t h2f2(float2 p) { return h2(p.x, p.y); }

__device__ __forceinline__ void mma16(float c[4], const uint32_t a[4],
                                      uint32_t b0, uint32_t b1) {
    asm volatile(
        "mma.sync.aligned.m16n8k16.row.col.f32.f16.f16.f32 "
        "{%0,%1,%2,%3}, {%4,%5,%6,%7}, {%8,%9}, {%0,%1,%2,%3};"
        : "+f"(c[0]), "+f"(c[1]), "+f"(c[2]), "+f"(c[3])
        : "r"(a[0]), "r"(a[1]), "r"(a[2]), "r"(a[3]), "r"(b0), "r"(b1));
}

__device__ __forceinline__ void ldmat4(uint32_t a[4], uint32_t saddr) {
    asm volatile("ldmatrix.sync.aligned.m8n8.x4.shared.b16 {%0,%1,%2,%3}, [%4];"
                 : "=r"(a[0]), "=r"(a[1]), "=r"(a[2]), "=r"(a[3]) : "r"(saddr));
}

__device__ __forceinline__ float ssp(float x) {
    float h = 0.5f * x;
    if (h > 14.0f) return x;
    return 2.0f * __logf(1.0f + __expf(h));
}

__device__ __forceinline__ void red2(float* p, float a, float b) {
    asm volatile("red.global.add.v2.f32 [%0], {%1,%2};"
                 :: "l"(p), "f"(a), "f"(b) : "memory");
}

__device__ __forceinline__ uint32_t smem_u32(const void* p) {
    uint32_t a;
    asm("{.reg .u64 t; cvta.to.shared.u64 t, %1; cvt.u32.u64 %0, t;}" : "=r"(a) : "l"(p));
    return a;
}

__device__ __forceinline__ void cp16(const float* s, const void* g) {
    uint32_t sa = smem_u32(s);
    asm volatile("cp.async.cg.shared.global [%0], [%1], 16;" :: "r"(sa), "l"(g));
}

__device__ __forceinline__ void pbar(int pair) {
    asm volatile("bar.sync %0, 64;" :: "r"(pair + 1) : "memory");
}

__global__ void __launch_bounds__(THREADS, 2)
cfconv_kernel(const float* __restrict__ nw,
              const float* __restrict__ rbf,
              const float* __restrict__ W1,
              const float* __restrict__ b1,
              const float* __restrict__ W2,
              const float* __restrict__ b2,
              const int*   __restrict__ src,
              const int*   __restrict__ dst,
              float* __restrict__ out,
              int E) {
    extern __shared__ __align__(16) float sm[];
    float* SBUF = sm + SBUF_OFF;
    uint4* W1F  = (uint4*)(sm + W1F_OFF);
    uint4* W2F  = (uint4*)(sm + W2F_OFF);
    float* B1S  = sm + B1_OFF;
    float* B2S  = sm + B2_OFF;

    const int tid  = threadIdx.x;
    const int warp = tid >> 5;
    const int lane = tid & 31;
    const int r = lane >> 2, c = lane & 3;
    const int pair = warp >> 1;
    const int h    = warp & 1;          // N-half: cols [h*32, h*32+32)

    // ---- one-time: pack W1,W2 as fp16 B-fragments (uint4 covers j=2jp,2jp+1) ----
    for (int idx = tid; idx < 512; idx += THREADS) {
        int g = idx >> 5, ln = idx & 31;
        int s = g >> 2, jp = g & 3;
        int rr = ln >> 2, cc = ln & 3;
        int k0 = s * 16 + 2 * cc;
        int n0 = jp * 16 + rr;
        const float* Ws[2] = {W1, W2};
        uint4* Fs[2] = {W1F, W2F};
#pragma unroll
        for (int w = 0; w < 2; w++) {
            const float* W = Ws[w];
            uint4 v;
            v.x = h2(W[k0 * 64 + n0],       W[(k0 + 1) * 64 + n0]);
            v.y = h2(W[(k0 + 8) * 64 + n0], W[(k0 + 9) * 64 + n0]);
            v.z = h2(W[k0 * 64 + n0 + 8],       W[(k0 + 1) * 64 + n0 + 8]);
            v.w = h2(W[(k0 + 8) * 64 + n0 + 8], W[(k0 + 9) * 64 + n0 + 8]);
            Fs[w][idx] = v;
        }
    }
    if (tid < 64) { B1S[tid] = b1[tid]; B2S[tid] = b2[tid]; }
    __syncthreads();

    const int ntiles = (E + TILE - 1) / TILE;
    float* wsbuf = SBUF + warp * 32 * STRIDE;       // this warp's 32 staged rows
    float* PS    = SBUF + pair * 64 * STRIDE;       // pair's 64-row fp32 window
    __half* H    = (__half*)PS;                     // fp16 overlay, stride 72 halves
    const uint32_t hb = smem_u32(H);
    // ldmatrix per-lane byte offset within H: row (lane&15), col-half (lane>>4)*8
    const uint32_t lmo = (uint32_t)((lane & 15) * STRIDE + (lane >> 4) * 8) * 2;

    // ---- stage first tile (warp-local 32 rows) ----
    int t = blockIdx.x;
    if (t < ntiles) {
        const int et = t * TILE + warp * 32;
#pragma unroll
        for (int i = 0; i < 16; i++) {
            int g = lane + i * 32;
            int row = g >> 4, q = g & 15;
            int e = et + row;
            float* d = &wsbuf[row * STRIDE + q * 4];
            if (e < E) cp16(d, rbf + (long)e * 64 + q * 4);
            else       *(float4*)d = make_float4(0.f, 0.f, 0.f, 0.f);
        }
        asm volatile("cp.async.commit_group;" ::: "memory");
    }

    for (; t < ntiles; t += gridDim.x) {
        const int etp = t * TILE + pair * 64;       // pair's first edge

        // src/dst for the pair's 64 edges
        int e0 = etp + lane, e1 = etp + 32 + lane;
        int se0 = (e0 < E) ? __ldg(src + e0) : 0;
        int de0 = (e0 < E) ? __ldg(dst + e0) : 0;
        int se1 = (e1 < E) ? __ldg(src + e1) : 0;
        int de1 = (e1 < E) ? __ldg(dst + e1) : 0;

        asm volatile("cp.async.wait_group 0;" ::: "memory");
        pbar(pair);                                  // both halves staged

        // ---- GEMM1: A = pair's fp32 rbf (cvt), B = this warp's N-half ----
        float acc[4][4][4];
#pragma unroll
        for (int mt = 0; mt < 4; mt++)
#pragma unroll
            for (int j = 0; j < 4; j++)
#pragma unroll
                for (int p = 0; p < 4; p++) acc[mt][j][p] = 0.f;

#pragma unroll
        for (int s = 0; s < 4; s++) {
            uint4 bA = W1F[(s * 4 + h * 2 + 0) * 32 + lane];
            uint4 bB = W1F[(s * 4 + h * 2 + 1) * 32 + lane];
#pragma unroll
            for (int mt = 0; mt < 4; mt++) {
                const float* base = PS + (mt * 16 + r) * STRIDE + s * 16 + 2 * c;
                uint32_t a[4];
                a[0] = h2f2(*(const float2*)(base));
                a[1] = h2f2(*(const float2*)(base + 8 * STRIDE));
                a[2] = h2f2(*(const float2*)(base + 8));
                a[3] = h2f2(*(const float2*)(base + 8 * STRIDE + 8));
                mma16(acc[mt][0], a, bA.x, bA.y);
                mma16(acc[mt][1], a, bA.z, bA.w);
                mma16(acc[mt][2], a, bB.x, bB.y);
                mma16(acc[mt][3], a, bB.z, bB.w);
            }
        }
        pbar(pair);                                  // pair done reading rbf

        // ---- hidden = ssp(acc + b1) -> fp16 overlay (this warp's cols) ----
#pragma unroll
        for (int mt = 0; mt < 4; mt++) {
#pragma unroll
            for (int j = 0; j < 4; j++) {
                int col = h * 32 + j * 8 + 2 * c;
                float2 bb = *(const float2*)&B1S[col];
                *(uint32_t*)&H[(mt * 16 + r) * STRIDE + col] =
                    h2(ssp(acc[mt][j][0] + bb.x), ssp(acc[mt][j][1] + bb.y));
                *(uint32_t*)&H[(mt * 16 + r + 8) * STRIDE + col] =
                    h2(ssp(acc[mt][j][2] + bb.x), ssp(acc[mt][j][3] + bb.y));
            }
        }
        pbar(pair);                                  // hidden fully written

        // ---- GEMM2: A = fp16 hidden (ldmatrix), B = this warp's N-half ----
#pragma unroll
        for (int mt = 0; mt < 4; mt++)
#pragma unroll
            for (int j = 0; j < 4; j++)
#pragma unroll
                for (int p = 0; p < 4; p++) acc[mt][j][p] = 0.f;

#pragma unroll
        for (int s = 0; s < 4; s++) {
            uint4 bA = W2F[(s * 4 + h * 2 + 0) * 32 + lane];
            uint4 bB = W2F[(s * 4 + h * 2 + 1) * 32 + lane];
#pragma unroll
            for (int mt = 0; mt < 4; mt++) {
                uint32_t a[4];
                ldmat4(a, hb + (uint32_t)(mt * 16 * STRIDE + s * 16) * 2 + lmo);
                mma16(acc[mt][0], a, bA.x, bA.y);
                mma16(acc[mt][1], a, bA.z, bA.w);
                mma16(acc[mt][2], a, bB.x, bB.y);
                mma16(acc[mt][3], a, bB.z, bB.w);
            }
        }
        pbar(pair);                                  // pair done reading hidden

        // ---- slice free: stage NEXT tile (overlaps epilogue) ----
        int tn = t + gridDim.x;
        if (tn < ntiles) {
            const int etn = tn * TILE + warp * 32;
#pragma unroll
            for (int i = 0; i < 16; i++) {
                int g = lane + i * 32;
                int row = g >> 4, q = g & 15;
                int e = etn + row;
                float* d = &wsbuf[row * STRIDE + q * 4];
                if (e < E) cp16(d, rbf + (long)e * 64 + q * 4);
                else       *(float4*)d = make_float4(0.f, 0.f, 0.f, 0.f);
            }
            asm volatile("cp.async.commit_group;" ::: "memory");
        }

        // ---- epilogue: 64 edges x this warp's 32 dims, from registers ----
#pragma unroll
        for (int mt = 0; mt < 4; mt++) {
#pragma unroll
            for (int rr = 0; rr < 2; rr++) {
                int x = mt * 16 + rr * 8 + r;        // pair-local edge 0..63
                int sN = (mt < 2) ? __shfl_sync(0xffffffff, se0, x)
                                  : __shfl_sync(0xffffffff, se1, x - 32);
                int dN = (mt < 2) ? __shfl_sync(0xffffffff, de0, x)
                                  : __shfl_sync(0xffffffff, de1, x - 32);
                if (etp + x < E) {
                    const float* nr = nw + (long)sN * 64;
                    float* ob = out + (long)dN * 64;
#pragma unroll
                    for (int j = 0; j < 4; j++) {
                        int col = h * 32 + j * 8 + 2 * c;
                        float2 bb = *(const float2*)&B2S[col];
                        float2 nv = __ldg((const float2*)(nr + col));
                        red2(ob + col,
                             nv.x * (acc[mt][j][rr * 2 + 0] + bb.x),
                             nv.y * (acc[mt][j][rr * 2 + 1] + bb.y));
                    }
                }
            }
        }
    }
}

__global__ void zero_kernel(float4* __restrict__ o, int n4) {
    int i = blockIdx.x * blockDim.x + threadIdx.x;
    if (i < n4) o[i] = make_float4(0.f, 0.f, 0.f, 0.f);
}

extern "C" void kernel_launch(void* const* d_in, const int* in_sizes, int n_in,
                              void* d_out, int out_size) {
    const float* nw  = (const float*)d_in[0];
    const float* rbf = (const float*)d_in[1];
    const float* W1  = (const float*)d_in[2];
    const float* b1  = (const float*)d_in[3];
    const float* W2  = (const float*)d_in[4];
    const float* b2  = (const float*)d_in[5];
    const int*   src = (const int*)d_in[6];
    const int*   dst = (const int*)d_in[7];
    float* out = (float*)d_out;

    const int E = in_sizes[1] / 64;

    cudaFuncSetAttribute(cfconv_kernel,
                         cudaFuncAttributeMaxDynamicSharedMemorySize, SMEM_BYTES);

    int n4 = out_size / 4;
    zero_kernel<<<(n4 + 255) / 256, 256>>>((float4*)out, n4);

    cfconv_kernel<<<304, THREADS, SMEM_BYTES>>>(nw, rbf, W1, b1, W2, b2, src, dst, out, E);
}

// round 11
// speedup vs baseline: 1.1733x; 1.1733x over previous
#include <cuda_runtime.h>
#include <cuda_fp16.h>
#include <cstdint>

// CFConv fused via mma.sync fp16 (m16n8k16, fp32 accum). Warp-autonomous
// 32-edge slices; hidden state passed GEMM1 -> GEMM2 entirely in registers
// (D-fragment layout == A-fragment layout). No hidden smem round trip.
// out[dst] += nw[src] * ( ssp(rbf @ W1 + b1) @ W2 + b2 )

static constexpr int TILE    = 256;
static constexpr int THREADS = 256;
static constexpr int STRIDE  = 72;    // fp32 row stride (conflict-free LDS.64)

// shared layout (floats)
static constexpr int SBUF_OFF = 0;                    // 256 x 72 fp32
static constexpr int W1F_OFF  = TILE * STRIDE;        // 18432: 512 uint4 fp16 frags
static constexpr int W2F_OFF  = W1F_OFF + 2048;       // 20480
static constexpr int B1_OFF   = W2F_OFF + 2048;       // 22528
static constexpr int B2_OFF   = B1_OFF + 64;          // 22592
static constexpr int SMEM_FLOATS = B2_OFF + 64;       // 22656
static constexpr int SMEM_BYTES  = SMEM_FLOATS * 4;   // 90624

__device__ __forceinline__ uint32_t h2(float lo, float hi) {
    uint32_t d;   // first PTX src -> upper half
    asm("cvt.rn.f16x2.f32 %0, %1, %2;" : "=r"(d) : "f"(hi), "f"(lo));
    return d;
}
__device__ __forceinline__ uint32_t h2f2(float2 p) { return h2(p.x, p.y); }

__device__ __forceinline__ void mma16(float c[4], const uint32_t a[4],
                                      uint32_t b0, uint32_t b1) {
    asm volatile(
        "mma.sync.aligned.m16n8k16.row.col.f32.f16.f16.f32 "
        "{%0,%1,%2,%3}, {%4,%5,%6,%7}, {%8,%9}, {%0,%1,%2,%3};"
        : "+f"(c[0]), "+f"(c[1]), "+f"(c[2]), "+f"(c[3])
        : "r"(a[0]), "r"(a[1]), "r"(a[2]), "r"(a[3]), "r"(b0), "r"(b1));
}

__device__ __forceinline__ float ssp(float x) {
    float h = 0.5f * x;
    if (h > 14.0f) return x;
    return 2.0f * __logf(1.0f + __expf(h));
}

__device__ __forceinline__ void red2(float* p, float a, float b) {
    asm volatile("red.global.add.v2.f32 [%0], {%1,%2};"
                 :: "l"(p), "f"(a), "f"(b) : "memory");
}

__device__ __forceinline__ void cp16(const float* s, const void* g) {
    uint32_t sa;
    asm("{.reg .u64 t; cvta.to.shared.u64 t, %1; cvt.u32.u64 %0, t;}" : "=r"(sa) : "l"(s));
    asm volatile("cp.async.cg.shared.global [%0], [%1], 16;" :: "r"(sa), "l"(g));
}

__global__ void __launch_bounds__(THREADS, 2)
cfconv_kernel(const float* __restrict__ nw,
              const float* __restrict__ rbf,
              const float* __restrict__ W1,
              const float* __restrict__ b1,
              const float* __restrict__ W2,
              const float* __restrict__ b2,
              const int*   __restrict__ src,
              const int*   __restrict__ dst,
              float* __restrict__ out,
              int E) {
    extern __shared__ __align__(16) float sm[];
    float* SBUF = sm + SBUF_OFF;
    uint4* W1F  = (uint4*)(sm + W1F_OFF);
    uint4* W2F  = (uint4*)(sm + W2F_OFF);
    float* B1S  = sm + B1_OFF;
    float* B2S  = sm + B2_OFF;

    const int tid  = threadIdx.x;
    const int warp = tid >> 5;
    const int lane = tid & 31;
    const int r = lane >> 2, c = lane & 3;
    const int wb = warp * 32;

    // ---- one-time: pack W1,W2 as fp16 B-fragments (LDS.128 order) ----
    for (int idx = tid; idx < 512; idx += THREADS) {
        int g = idx >> 5, ln = idx & 31;
        int s = g >> 2, jp = g & 3;
        int rr = ln >> 2, cc = ln & 3;
        int k0 = s * 16 + 2 * cc;
        int n0 = jp * 16 + rr;
        const float* Ws[2] = {W1, W2};
        uint4* Fs[2] = {W1F, W2F};
#pragma unroll
        for (int w = 0; w < 2; w++) {
            const float* W = Ws[w];
            uint4 v;
            v.x = h2(W[k0 * 64 + n0],       W[(k0 + 1) * 64 + n0]);
            v.y = h2(W[(k0 + 8) * 64 + n0], W[(k0 + 9) * 64 + n0]);
            v.z = h2(W[k0 * 64 + n0 + 8],       W[(k0 + 1) * 64 + n0 + 8]);
            v.w = h2(W[(k0 + 8) * 64 + n0 + 8], W[(k0 + 9) * 64 + n0 + 8]);
            Fs[w][idx] = v;
        }
    }
    if (tid < 64) { B1S[tid] = b1[tid]; B2S[tid] = b2[tid]; }
    __syncthreads();

    const int ntiles = (E + TILE - 1) / TILE;
    float* wsbuf = SBUF + wb * STRIDE;

    // ---- stage first tile ----
    int t = blockIdx.x;
    if (t < ntiles) {
        const int et = t * TILE + wb;
#pragma unroll
        for (int i = 0; i < 16; i++) {
            int g = lane + i * 32;
            int row = g >> 4, q = g & 15;
            int e = et + row;
            float* d = &wsbuf[row * STRIDE + q * 4];
            if (e < E) cp16(d, rbf + (long)e * 64 + q * 4);
            else       *(float4*)d = make_float4(0.f, 0.f, 0.f, 0.f);
        }
        asm volatile("cp.async.commit_group;" ::: "memory");
    }

    for (; t < ntiles; t += gridDim.x) {
        const int et = t * TILE + wb;

        int myE = et + lane;
        int se = (myE < E) ? __ldg(src + myE) : 0;
        int de = (myE < E) ? __ldg(dst + myE) : 0;

        asm volatile("cp.async.wait_group 0;" ::: "memory");
        __syncwarp();

        // ---- GEMM1: A = fp32 SBUF (cvt to fp16), B = W1F ----
        float acc[2][8][4];
#pragma unroll
        for (int mt = 0; mt < 2; mt++)
#pragma unroll
            for (int j = 0; j < 8; j++)
#pragma unroll
                for (int p = 0; p < 4; p++) acc[mt][j][p] = 0.f;

#pragma unroll
        for (int s = 0; s < 4; s++) {
            uint32_t a[2][4];
#pragma unroll
            for (int mt = 0; mt < 2; mt++) {
                const float* base = wsbuf + (mt * 16 + r) * STRIDE + s * 16 + 2 * c;
                a[mt][0] = h2f2(*(const float2*)(base));
                a[mt][1] = h2f2(*(const float2*)(base + 8 * STRIDE));
                a[mt][2] = h2f2(*(const float2*)(base + 8));
                a[mt][3] = h2f2(*(const float2*)(base + 8 * STRIDE + 8));
            }
#pragma unroll
            for (int jp = 0; jp < 4; jp++) {
                uint4 bv = W1F[(s * 4 + jp) * 32 + lane];
                mma16(acc[0][2 * jp],     a[0], bv.x, bv.y);
                mma16(acc[1][2 * jp],     a[1], bv.x, bv.y);
                mma16(acc[0][2 * jp + 1], a[0], bv.z, bv.w);
                mma16(acc[1][2 * jp + 1], a[1], bv.z, bv.w);
            }
        }
        __syncwarp();   // warp done reading its SBUF slice

        // ---- hidden = ssp(acc + b1) -> REGISTER A-fragments for GEMM2 ----
        // D-frag (rows r,r+8; col pair j*8+2c) == A-frag (k pair s*16+2c / +8)
        // with s=j/2:  hp[mt][s] = {a0,a1,a2,a3}
        uint32_t hp[2][4][4];
#pragma unroll
        for (int mt = 0; mt < 2; mt++) {
#pragma unroll
            for (int j = 0; j < 8; j++) {
                int col = j * 8 + 2 * c;
                float2 bb = *(const float2*)&B1S[col];
                uint32_t h01 = h2(ssp(acc[mt][j][0] + bb.x), ssp(acc[mt][j][1] + bb.y));
                uint32_t h23 = h2(ssp(acc[mt][j][2] + bb.x), ssp(acc[mt][j][3] + bb.y));
                hp[mt][j >> 1][(j & 1) * 2 + 0] = h01;
                hp[mt][j >> 1][(j & 1) * 2 + 1] = h23;
            }
        }

        // ---- SBUF slice free: stage NEXT tile (hides behind GEMM2+epilogue) ----
        int tn = t + gridDim.x;
        if (tn < ntiles) {
            const int etn = tn * TILE + wb;
#pragma unroll
            for (int i = 0; i < 16; i++) {
                int g = lane + i * 32;
                int row = g >> 4, q = g & 15;
                int e = etn + row;
                float* d = &wsbuf[row * STRIDE + q * 4];
                if (e < E) cp16(d, rbf + (long)e * 64 + q * 4);
                else       *(float4*)d = make_float4(0.f, 0.f, 0.f, 0.f);
            }
            asm volatile("cp.async.commit_group;" ::: "memory");
        }

        // ---- GEMM2: A = register hp, B = W2F ----
#pragma unroll
        for (int mt = 0; mt < 2; mt++)
#pragma unroll
            for (int j = 0; j < 8; j++)
#pragma unroll
                for (int p = 0; p < 4; p++) acc[mt][j][p] = 0.f;

#pragma unroll
        for (int s = 0; s < 4; s++) {
#pragma unroll
            for (int jp = 0; jp < 4; jp++) {
                uint4 bv = W2F[(s * 4 + jp) * 32 + lane];
                mma16(acc[0][2 * jp],     hp[0][s], bv.x, bv.y);
                mma16(acc[1][2 * jp],     hp[1][s], bv.x, bv.y);
                mma16(acc[0][2 * jp + 1], hp[0][s], bv.z, bv.w);
                mma16(acc[1][2 * jp + 1], hp[1][s], bv.z, bv.w);
            }
        }

        // ---- epilogue from registers ----
#pragma unroll
        for (int mt = 0; mt < 2; mt++) {
#pragma unroll
            for (int rr = 0; rr < 2; rr++) {
                int x = mt * 16 + rr * 8 + r;
                int sN = __shfl_sync(0xffffffff, se, x);
                int dN = __shfl_sync(0xffffffff, de, x);
                if (et + x < E) {
                    const float* nr = nw + (long)sN * 64;
                    float* ob = out + (long)dN * 64;
#pragma unroll
                    for (int j = 0; j < 8; j++) {
                        int col = j * 8 + 2 * c;
                        float2 bb = *(const float2*)&B2S[col];
                        float2 nv = __ldg((const float2*)(nr + col));
                        red2(ob + col,
                             nv.x * (acc[mt][j][rr * 2 + 0] + bb.x),
                             nv.y * (acc[mt][j][rr * 2 + 1] + bb.y));
                    }
                }
            }
        }
    }
}

__global__ void zero_kernel(float4* __restrict__ o, int n4) {
    int i = blockIdx.x * blockDim.x + threadIdx.x;
    if (i < n4) o[i] = make_float4(0.f, 0.f, 0.f, 0.f);
}

extern "C" void kernel_launch(void* const* d_in, const int* in_sizes, int n_in,
                              void* d_out, int out_size) {
    const float* nw  = (const float*)d_in[0];
    const float* rbf = (const float*)d_in[1];
    const float* W1  = (const float*)d_in[2];
    const float* b1  = (const float*)d_in[3];
    const float* W2  = (const float*)d_in[4];
    const float* b2  = (const float*)d_in[5];
    const int*   src = (const int*)d_in[6];
    const int*   dst = (const int*)d_in[7];
    float* out = (float*)d_out;

    const int E = in_sizes[1] / 64;

    cudaFuncSetAttribute(cfconv_kernel,
                         cudaFuncAttributeMaxDynamicSharedMemorySize, SMEM_BYTES);

    int n4 = out_size / 4;
    zero_kernel<<<(n4 + 255) / 256, 256>>>((float4*)out, n4);

    cfconv_kernel<<<304, THREADS, SMEM_BYTES>>>(nw, rbf, W1, b1, W2, b2, src, dst, out, E);
}

// round 12
// speedup vs baseline: 1.4580x; 1.2427x over previous
#include <cuda_runtime.h>
#include <cuda_fp16.h>
#include <cstdint>

// CFConv fused via mma.sync fp16 (m16n8k16, fp32 accum). Warp-autonomous
// 32-edge slices; hidden passed GEMM1 -> GEMM2 in registers; biases injected
// as mma C-operands (no zero-init MOVs, no bias FADDs).
// out[dst] += nw[src] * ( ssp(rbf @ W1 + b1) @ W2 + b2 )

static constexpr int TILE    = 256;
static constexpr int THREADS = 256;
static constexpr int STRIDE  = 72;    // fp32 row stride (conflict-free LDS.64)

// shared layout (floats)
static constexpr int SBUF_OFF = 0;                    // 256 x 72 fp32
static constexpr int W1F_OFF  = TILE * STRIDE;        // 18432: 512 uint4 fp16 frags
static constexpr int W2F_OFF  = W1F_OFF + 2048;       // 20480
static constexpr int B1_OFF   = W2F_OFF + 2048;       // 22528
static constexpr int B2_OFF   = B1_OFF + 64;          // 22592
static constexpr int SMEM_FLOATS = B2_OFF + 64;       // 22656
static constexpr int SMEM_BYTES  = SMEM_FLOATS * 4;   // 90624

__device__ __forceinline__ uint32_t h2(float lo, float hi) {
    uint32_t d;   // first PTX src -> upper half
    asm("cvt.rn.f16x2.f32 %0, %1, %2;" : "=r"(d) : "f"(hi), "f"(lo));
    return d;
}
__device__ __forceinline__ uint32_t h2f2(float2 p) { return h2(p.x, p.y); }

__device__ __forceinline__ void mma16(float c[4], const uint32_t a[4],
                                      uint32_t b0, uint32_t b1) {
    asm volatile(
        "mma.sync.aligned.m16n8k16.row.col.f32.f16.f16.f32 "
        "{%0,%1,%2,%3}, {%4,%5,%6,%7}, {%8,%9}, {%0,%1,%2,%3};"
        : "+f"(c[0]), "+f"(c[1]), "+f"(c[2]), "+f"(c[3])
        : "r"(a[0]), "r"(a[1]), "r"(a[2]), "r"(a[3]), "r"(b0), "r"(b1));
}

// first K-step: D = A*B + {cx,cy,cx,cy}  (bias injected via C operand)
__device__ __forceinline__ void mma16c(float d[4], const uint32_t a[4],
                                       uint32_t b0, uint32_t b1,
                                       float cx, float cy) {
    asm volatile(
        "mma.sync.aligned.m16n8k16.row.col.f32.f16.f16.f32 "
        "{%0,%1,%2,%3}, {%4,%5,%6,%7}, {%8,%9}, {%10,%11,%10,%11};"
        : "=f"(d[0]), "=f"(d[1]), "=f"(d[2]), "=f"(d[3])
        : "r"(a[0]), "r"(a[1]), "r"(a[2]), "r"(a[3]), "r"(b0), "r"(b1),
          "f"(cx), "f"(cy));
}

// shifted softplus, base-2 folded: 2*log1p(exp(x/2)) ; x when x/2 > 14
__device__ __forceinline__ float ssp(float x) {
    float t, w;
    asm("ex2.approx.f32 %0, %1;" : "=f"(t) : "f"(0.72134752f * x));
    asm("lg2.approx.f32 %0, %1;" : "=f"(w) : "f"(1.0f + t));
    float res = 1.38629436f * w;
    return (x > 28.0f) ? x : res;
}

__device__ __forceinline__ void red2(float* p, float a, float b) {
    asm volatile("red.global.add.v2.f32 [%0], {%1,%2};"
                 :: "l"(p), "f"(a), "f"(b) : "memory");
}

__device__ __forceinline__ void cp16(const float* s, const void* g) {
    uint32_t sa;
    asm("{.reg .u64 t; cvta.to.shared.u64 t, %1; cvt.u32.u64 %0, t;}" : "=r"(sa) : "l"(s));
    asm volatile("cp.async.cg.shared.global [%0], [%1], 16;" :: "r"(sa), "l"(g));
}

__global__ void __launch_bounds__(THREADS, 2)
cfconv_kernel(const float* __restrict__ nw,
              const float* __restrict__ rbf,
              const float* __restrict__ W1,
              const float* __restrict__ b1,
              const float* __restrict__ W2,
              const float* __restrict__ b2,
              const int*   __restrict__ src,
              const int*   __restrict__ dst,
              float* __restrict__ out,
              int E) {
    extern __shared__ __align__(16) float sm[];
    float* SBUF = sm + SBUF_OFF;
    uint4* W1F  = (uint4*)(sm + W1F_OFF);
    uint4* W2F  = (uint4*)(sm + W2F_OFF);
    float* B1S  = sm + B1_OFF;
    float* B2S  = sm + B2_OFF;

    const int tid  = threadIdx.x;
    const int warp = tid >> 5;
    const int lane = tid & 31;
    const int r = lane >> 2, c = lane & 3;
    const int wb = warp * 32;

    // ---- one-time: pack W1,W2 as fp16 B-fragments (LDS.128 order) ----
    for (int idx = tid; idx < 512; idx += THREADS) {
        int g = idx >> 5, ln = idx & 31;
        int s = g >> 2, jp = g & 3;
        int rr = ln >> 2, cc = ln & 3;
        int k0 = s * 16 + 2 * cc;
        int n0 = jp * 16 + rr;
        const float* Ws[2] = {W1, W2};
        uint4* Fs[2] = {W1F, W2F};
#pragma unroll
        for (int w = 0; w < 2; w++) {
            const float* W = Ws[w];
            uint4 v;
            v.x = h2(W[k0 * 64 + n0],       W[(k0 + 1) * 64 + n0]);
            v.y = h2(W[(k0 + 8) * 64 + n0], W[(k0 + 9) * 64 + n0]);
            v.z = h2(W[k0 * 64 + n0 + 8],       W[(k0 + 1) * 64 + n0 + 8]);
            v.w = h2(W[(k0 + 8) * 64 + n0 + 8], W[(k0 + 9) * 64 + n0 + 8]);
            Fs[w][idx] = v;
        }
    }
    if (tid < 64) { B1S[tid] = b1[tid]; B2S[tid] = b2[tid]; }
    __syncthreads();

    const int ntiles = (E + TILE - 1) / TILE;
    float* wsbuf = SBUF + wb * STRIDE;

    // ---- stage first tile ----
    int t = blockIdx.x;
    if (t < ntiles) {
        const int et = t * TILE + wb;
#pragma unroll
        for (int i = 0; i < 16; i++) {
            int g = lane + i * 32;
            int row = g >> 4, q = g & 15;
            int e = et + row;
            float* d = &wsbuf[row * STRIDE + q * 4];
            if (e < E) cp16(d, rbf + (long)e * 64 + q * 4);
            else       *(float4*)d = make_float4(0.f, 0.f, 0.f, 0.f);
        }
        asm volatile("cp.async.commit_group;" ::: "memory");
    }

    for (; t < ntiles; t += gridDim.x) {
        const int et = t * TILE + wb;

        int myE = et + lane;
        int se = (myE < E) ? __ldg(src + myE) : 0;
        int de = (myE < E) ? __ldg(dst + myE) : 0;

        asm volatile("cp.async.wait_group 0;" ::: "memory");
        __syncwarp();

        // ---- GEMM1: peel s=0 with bias C-operand, then s=1..3 ----
        float acc[2][8][4];
        {
            uint32_t a[2][4];
#pragma unroll
            for (int mt = 0; mt < 2; mt++) {
                const float* base = wsbuf + (mt * 16 + r) * STRIDE + 2 * c;
                a[mt][0] = h2f2(*(const float2*)(base));
                a[mt][1] = h2f2(*(const float2*)(base + 8 * STRIDE));
                a[mt][2] = h2f2(*(const float2*)(base + 8));
                a[mt][3] = h2f2(*(const float2*)(base + 8 * STRIDE + 8));
            }
#pragma unroll
            for (int jp = 0; jp < 4; jp++) {
                uint4 bv = W1F[jp * 32 + lane];
                float2 bbA = *(const float2*)&B1S[(2 * jp) * 8 + 2 * c];
                float2 bbB = *(const float2*)&B1S[(2 * jp + 1) * 8 + 2 * c];
                mma16c(acc[0][2 * jp],     a[0], bv.x, bv.y, bbA.x, bbA.y);
                mma16c(acc[1][2 * jp],     a[1], bv.x, bv.y, bbA.x, bbA.y);
                mma16c(acc[0][2 * jp + 1], a[0], bv.z, bv.w, bbB.x, bbB.y);
                mma16c(acc[1][2 * jp + 1], a[1], bv.z, bv.w, bbB.x, bbB.y);
            }
        }
#pragma unroll
        for (int s = 1; s < 4; s++) {
            uint32_t a[2][4];
#pragma unroll
            for (int mt = 0; mt < 2; mt++) {
                const float* base = wsbuf + (mt * 16 + r) * STRIDE + s * 16 + 2 * c;
                a[mt][0] = h2f2(*(const float2*)(base));
                a[mt][1] = h2f2(*(const float2*)(base + 8 * STRIDE));
                a[mt][2] = h2f2(*(const float2*)(base + 8));
                a[mt][3] = h2f2(*(const float2*)(base + 8 * STRIDE + 8));
            }
#pragma unroll
            for (int jp = 0; jp < 4; jp++) {
                uint4 bv = W1F[(s * 4 + jp) * 32 + lane];
                mma16(acc[0][2 * jp],     a[0], bv.x, bv.y);
                mma16(acc[1][2 * jp],     a[1], bv.x, bv.y);
                mma16(acc[0][2 * jp + 1], a[0], bv.z, bv.w);
                mma16(acc[1][2 * jp + 1], a[1], bv.z, bv.w);
            }
        }
        __syncwarp();   // warp done reading its SBUF slice

        // ---- hidden = ssp(acc) -> register A-fragments for GEMM2 ----
        uint32_t hp[2][4][4];
#pragma unroll
        for (int mt = 0; mt < 2; mt++) {
#pragma unroll
            for (int j = 0; j < 8; j++) {
                uint32_t h01 = h2(ssp(acc[mt][j][0]), ssp(acc[mt][j][1]));
                uint32_t h23 = h2(ssp(acc[mt][j][2]), ssp(acc[mt][j][3]));
                hp[mt][j >> 1][(j & 1) * 2 + 0] = h01;
                hp[mt][j >> 1][(j & 1) * 2 + 1] = h23;
            }
        }

        // ---- SBUF slice free: stage NEXT tile ----
        int tn = t + gridDim.x;
        if (tn < ntiles) {
            const int etn = tn * TILE + wb;
#pragma unroll
            for (int i = 0; i < 16; i++) {
                int g = lane + i * 32;
                int row = g >> 4, q = g & 15;
                int e = etn + row;
                float* d = &wsbuf[row * STRIDE + q * 4];
                if (e < E) cp16(d, rbf + (long)e * 64 + q * 4);
                else       *(float4*)d = make_float4(0.f, 0.f, 0.f, 0.f);
            }
            asm volatile("cp.async.commit_group;" ::: "memory");
        }

        // ---- GEMM2: peel s=0 with b2 C-operand, then s=1..3 ----
        {
#pragma unroll
            for (int jp = 0; jp < 4; jp++) {
                uint4 bv = W2F[jp * 32 + lane];
                float2 bbA = *(const float2*)&B2S[(2 * jp) * 8 + 2 * c];
                float2 bbB = *(const float2*)&B2S[(2 * jp + 1) * 8 + 2 * c];
                mma16c(acc[0][2 * jp],     hp[0][0], bv.x, bv.y, bbA.x, bbA.y);
                mma16c(acc[1][2 * jp],     hp[1][0], bv.x, bv.y, bbA.x, bbA.y);
                mma16c(acc[0][2 * jp + 1], hp[0][0], bv.z, bv.w, bbB.x, bbB.y);
                mma16c(acc[1][2 * jp + 1], hp[1][0], bv.z, bv.w, bbB.x, bbB.y);
            }
        }
#pragma unroll
        for (int s = 1; s < 4; s++) {
#pragma unroll
            for (int jp = 0; jp < 4; jp++) {
                uint4 bv = W2F[(s * 4 + jp) * 32 + lane];
                mma16(acc[0][2 * jp],     hp[0][s], bv.x, bv.y);
                mma16(acc[1][2 * jp],     hp[1][s], bv.x, bv.y);
                mma16(acc[0][2 * jp + 1], hp[0][s], bv.z, bv.w);
                mma16(acc[1][2 * jp + 1], hp[1][s], bv.z, bv.w);
            }
        }

        // ---- epilogue from registers (bias already in acc) ----
#pragma unroll
        for (int mt = 0; mt < 2; mt++) {
#pragma unroll
            for (int rr = 0; rr < 2; rr++) {
                int x = mt * 16 + rr * 8 + r;
                int sN = __shfl_sync(0xffffffff, se, x);
                int dN = __shfl_sync(0xffffffff, de, x);
                if (et + x < E) {
                    const float* nr = nw + (long)sN * 64;
                    float* ob = out + (long)dN * 64;
#pragma unroll
                    for (int j = 0; j < 8; j++) {
                        int col = j * 8 + 2 * c;
                        float2 nv = __ldg((const float2*)(nr + col));
                        red2(ob + col,
                             nv.x * acc[mt][j][rr * 2 + 0],
                             nv.y * acc[mt][j][rr * 2 + 1]);
                    }
                }
            }
        }
    }
}

__global__ void zero_kernel(float4* __restrict__ o, int n4) {
    int i = blockIdx.x * blockDim.x + threadIdx.x;
    if (i < n4) o[i] = make_float4(0.f, 0.f, 0.f, 0.f);
}

extern "C" void kernel_launch(void* const* d_in, const int* in_sizes, int n_in,
                              void* d_out, int out_size) {
    const float* nw  = (const float*)d_in[0];
    const float* rbf = (const float*)d_in[1];
    const float* W1  = (const float*)d_in[2];
    const float* b1  = (const float*)d_in[3];
    const float* W2  = (const float*)d_in[4];
    const float* b2  = (const float*)d_in[5];
    const int*   src = (const int*)d_in[6];
    const int*   dst = (const int*)d_in[7];
    float* out = (float*)d_out;

    const int E = in_sizes[1] / 64;

    cudaFuncSetAttribute(cfconv_kernel,
                         cudaFuncAttributeMaxDynamicSharedMemorySize, SMEM_BYTES);

    int n4 = out_size / 4;
    zero_kernel<<<(n4 + 255) / 256, 256>>>((float4*)out, n4);

    cfconv_kernel<<<304, THREADS, SMEM_BYTES>>>(nw, rbf, W1, b1, W2, b2, src, dst, out, E);
}